// round 1
// baseline (speedup 1.0000x reference)
#include <cuda_runtime.h>
#include <cstdint>

// Problem constants
#define NN   64
#define DD   512
#define TT   256
#define QQ   6
#define CC   1024
#define NT   (NN*TT)              // 16384
#define OUT_QUANT   (NN*DD*TT)    // 8388608
#define OUT_IDX     (NT*QQ)       // 98304

// Scratch (device globals — no runtime allocation allowed)
__device__ float g_res[(size_t)NT * DD];      // residual, flat (NT, D)
__device__ float g_cbnorm[QQ * CC];           // ||c||^2 per code per stage
__device__ int   g_indices[NT * QQ];          // (N,T,Q) flattened
__device__ int   g_hist[CC];
__device__ float g_loss[QQ];
__device__ float g_perp[QQ];

// ---------------------------------------------------------------------------
// init: zero hist + loss (required every launch; graph replays)
// ---------------------------------------------------------------------------
__global__ void init_kernel() {
    int t = threadIdx.x;
    if (t < CC) g_hist[t] = 0;
    if (t < QQ) g_loss[t] = 0.0f;
}

// ---------------------------------------------------------------------------
// transpose in: x (N, D, T) -> g_res (NT, D), row = n*T + t
// ---------------------------------------------------------------------------
__global__ void transpose_in_kernel(const float* __restrict__ x) {
    __shared__ float tile[32][33];
    int n  = blockIdx.z;
    int t0 = blockIdx.x * 32;
    int d0 = blockIdx.y * 32;
    int tx = threadIdx.x, ty = threadIdx.y;  // (32, 8)

    #pragma unroll
    for (int i = 0; i < 4; i++) {
        int d = d0 + ty + i * 8;
        tile[ty + i * 8][tx] = x[(size_t)n * DD * TT + (size_t)d * TT + (t0 + tx)];
    }
    __syncthreads();
    #pragma unroll
    for (int i = 0; i < 4; i++) {
        int t = t0 + ty + i * 8;
        g_res[(size_t)(n * TT + t) * DD + (d0 + tx)] = tile[tx][ty + i * 8];
    }
}

// ---------------------------------------------------------------------------
// codebook norms: one block per code (all 6 stages at once)
// ---------------------------------------------------------------------------
__global__ void cbnorm_kernel(const float* __restrict__ cb) {
    int code = blockIdx.x;             // 0..6143 (q*1024+c)
    int tid  = threadIdx.x;            // 128
    const float4* cv = (const float4*)(cb + (size_t)code * DD);
    float4 v = cv[tid];
    float s = v.x * v.x + v.y * v.y + v.z * v.z + v.w * v.w;
    #pragma unroll
    for (int off = 16; off > 0; off >>= 1) s += __shfl_down_sync(0xffffffffu, s, off);
    __shared__ float ws[4];
    if ((tid & 31) == 0) ws[tid >> 5] = s;
    __syncthreads();
    if (tid == 0) g_cbnorm[code] = ws[0] + ws[1] + ws[2] + ws[3];
}

// ---------------------------------------------------------------------------
// argmin GEMM: per row of g_res find argmin_c (||c||^2 - 2 r.c) over 1024 codes
// Tile: 64 rows x 128 codes, K-slices of 32, 256 threads, 4x8 micro-tile.
// ---------------------------------------------------------------------------
#define TM 64
#define TC 128
#define TK 32

__global__ void __launch_bounds__(256) argmin_kernel(const float* __restrict__ cb, int q) {
    __shared__ float As[TK][TM];
    __shared__ float Bs[TK][TC];
    int tid = threadIdx.x;
    int tx = tid & 15, ty = tid >> 4;
    int rowBase = blockIdx.x * TM;
    const float* norms = g_cbnorm + q * CC;

    float bestV[4];
    int   bestI[4];
    #pragma unroll
    for (int i = 0; i < 4; i++) { bestV[i] = 3.4e38f; bestI[i] = 0; }

    for (int ct = 0; ct < CC; ct += TC) {
        float acc[4][8];
        #pragma unroll
        for (int i = 0; i < 4; i++)
            #pragma unroll
            for (int j = 0; j < 8; j++) acc[i][j] = 0.0f;

        for (int k0 = 0; k0 < DD; k0 += TK) {
            __syncthreads();
            // load A tile (64 x 32): 2 float4 per thread, store transposed
            #pragma unroll
            for (int r = 0; r < 2; r++) {
                int v = tid + r * 256;
                int row = v >> 3, kq = (v & 7) * 4;
                float4 f = *(const float4*)(g_res + (size_t)(rowBase + row) * DD + k0 + kq);
                As[kq + 0][row] = f.x; As[kq + 1][row] = f.y;
                As[kq + 2][row] = f.z; As[kq + 3][row] = f.w;
            }
            // load B tile (128 x 32): 4 float4 per thread, store transposed
            #pragma unroll
            for (int r = 0; r < 4; r++) {
                int v = tid + r * 256;
                int code = v >> 3, kq = (v & 7) * 4;
                float4 f = *(const float4*)(cb + (size_t)(ct + code) * DD + k0 + kq);
                Bs[kq + 0][code] = f.x; Bs[kq + 1][code] = f.y;
                Bs[kq + 2][code] = f.z; Bs[kq + 3][code] = f.w;
            }
            __syncthreads();
            #pragma unroll
            for (int k = 0; k < TK; k++) {
                float a[4], b[8];
                #pragma unroll
                for (int i = 0; i < 4; i++) a[i] = As[k][ty * 4 + i];
                #pragma unroll
                for (int j = 0; j < 8; j++) b[j] = Bs[k][tx * 8 + j];
                #pragma unroll
                for (int i = 0; i < 4; i++)
                    #pragma unroll
                    for (int j = 0; j < 8; j++)
                        acc[i][j] = fmaf(a[i], b[j], acc[i][j]);
            }
        }
        // evaluate distances (ascending code order -> first-min tie-break)
        #pragma unroll
        for (int j = 0; j < 8; j++) {
            int c = ct + tx * 8 + j;
            float nc = norms[c];
            #pragma unroll
            for (int i = 0; i < 4; i++) {
                float d = nc - 2.0f * acc[i][j];
                if (d < bestV[i]) { bestV[i] = d; bestI[i] = c; }
            }
        }
    }

    // reduce across the 16 lanes that share each row (lanes are contiguous)
    #pragma unroll
    for (int i = 0; i < 4; i++) {
        float v = bestV[i];
        int   b = bestI[i];
        #pragma unroll
        for (int off = 8; off > 0; off >>= 1) {
            float ov = __shfl_down_sync(0xffffffffu, v, off, 16);
            int   ob = __shfl_down_sync(0xffffffffu, b, off, 16);
            if (ov < v || (ov == v && ob < b)) { v = ov; b = ob; }
        }
        if (tx == 0) {
            int row = rowBase + ty * 4 + i;
            g_indices[row * QQ + q] = b;
            atomicAdd(&g_hist[b], 1);
        }
    }
}

// ---------------------------------------------------------------------------
// residual update + commitment loss: res -= cb[idx]; loss += sum(res_new^2)
// ---------------------------------------------------------------------------
__global__ void update_kernel(const float* __restrict__ cb, int q) {
    int row = blockIdx.x;
    int tid = threadIdx.x;  // 128
    int c = g_indices[row * QQ + q];
    const float4* cv = (const float4*)(cb + (size_t)c * DD);
    float4* rv = (float4*)(g_res + (size_t)row * DD);
    float4 r = rv[tid], v = cv[tid];
    r.x -= v.x; r.y -= v.y; r.z -= v.z; r.w -= v.w;
    rv[tid] = r;
    float s = r.x * r.x + r.y * r.y + r.z * r.z + r.w * r.w;
    #pragma unroll
    for (int off = 16; off > 0; off >>= 1) s += __shfl_down_sync(0xffffffffu, s, off);
    __shared__ float ws[4];
    if ((tid & 31) == 0) ws[tid >> 5] = s;
    __syncthreads();
    if (tid == 0) atomicAdd(&g_loss[q], ws[0] + ws[1] + ws[2] + ws[3]);
}

// ---------------------------------------------------------------------------
// perplexity from histogram; zero histogram for next stage
// ---------------------------------------------------------------------------
__global__ void perp_kernel(int q) {
    int tid = threadIdx.x;  // 256
    float s = 0.0f;
    #pragma unroll
    for (int i = tid; i < CC; i += 256) {
        float p = (float)g_hist[i] * (1.0f / (float)NT);
        s += p * logf(p + 1e-10f);
        g_hist[i] = 0;
    }
    #pragma unroll
    for (int off = 16; off > 0; off >>= 1) s += __shfl_down_sync(0xffffffffu, s, off);
    __shared__ float ws[8];
    if ((tid & 31) == 0) ws[tid >> 5] = s;
    __syncthreads();
    if (tid == 0) {
        float t = 0.0f;
        #pragma unroll
        for (int i = 0; i < 8; i++) t += ws[i];
        g_perp[q] = expf(-t);
    }
}

// ---------------------------------------------------------------------------
// output: quantized_out (N,D,T) = x - residual_final  (transpose back)
// ---------------------------------------------------------------------------
__global__ void transpose_out_kernel(const float* __restrict__ x, float* __restrict__ out) {
    __shared__ float tile[32][33];
    int n  = blockIdx.z;
    int t0 = blockIdx.x * 32;
    int d0 = blockIdx.y * 32;
    int tx = threadIdx.x, ty = threadIdx.y;  // (32, 8)

    #pragma unroll
    for (int i = 0; i < 4; i++) {
        int t = t0 + ty + i * 8;
        tile[ty + i * 8][tx] = g_res[(size_t)(n * TT + t) * DD + (d0 + tx)];
    }
    __syncthreads();
    #pragma unroll
    for (int i = 0; i < 4; i++) {
        int d = d0 + ty + i * 8;
        size_t gi = (size_t)n * DD * TT + (size_t)d * TT + (t0 + tx);
        out[gi] = x[gi] - tile[tx][ty + i * 8];
    }
}

__global__ void idx_kernel(float* __restrict__ out) {
    int i = blockIdx.x * blockDim.x + threadIdx.x;
    if (i < OUT_IDX) out[OUT_QUANT + i] = (float)g_indices[i];
}

__global__ void finalize_kernel(float* __restrict__ out) {
    float l = 0.0f, p = 0.0f;
    #pragma unroll
    for (int q = 0; q < QQ; q++) { l += g_loss[q]; p += g_perp[q]; }
    l = l / ((float)NT * (float)DD) / (float)QQ;
    p = p / (float)QQ;
    out[OUT_QUANT + OUT_IDX + 0] = l;
    out[OUT_QUANT + OUT_IDX + 1] = p;
}

// ---------------------------------------------------------------------------
extern "C" void kernel_launch(void* const* d_in, const int* in_sizes, int n_in,
                              void* d_out, int out_size) {
    const float* x  = (const float*)d_in[0];   // (64, 512, 256) fp32
    const float* cb = (const float*)d_in[1];   // (6, 1024, 512) fp32
    float* out = (float*)d_out;

    init_kernel<<<1, 1024>>>();

    dim3 tb(32, 8);
    dim3 tg(TT / 32, DD / 32, NN);   // (8, 16, 64)
    transpose_in_kernel<<<tg, tb>>>(x);

    cbnorm_kernel<<<QQ * CC, 128>>>(cb);

    for (int q = 0; q < QQ; q++) {
        const float* cbq = cb + (size_t)q * CC * DD;
        argmin_kernel<<<NT / TM, 256>>>(cbq, q);
        update_kernel<<<NT, 128>>>(cbq, q);
        perp_kernel<<<1, 256>>>(q);
    }

    transpose_out_kernel<<<tg, tb>>>(x, out);
    idx_kernel<<<(OUT_IDX + 255) / 256, 256>>>(out);
    finalize_kernel<<<1, 1>>>(out);
}

// round 2
// speedup vs baseline: 1.6141x; 1.6141x over previous
#include <cuda_runtime.h>
#include <cstdint>

// Problem constants
#define NN   64
#define DD   512
#define TT   256
#define QQ   6
#define CC   1024
#define NT   (NN*TT)              // 16384
#define OUT_QUANT   (NN*DD*TT)    // 8388608
#define OUT_IDX     (NT*QQ)       // 98304

// Scratch (device globals — no runtime allocation allowed)
__device__ float g_res[(size_t)NT * DD];      // residual, flat (NT, D)
__device__ float g_cbnorm[QQ * CC];           // ||c||^2 per code per stage
__device__ int   g_indices[NT * QQ];          // (N,T,Q) flattened
__device__ int   g_hist[CC];
__device__ float g_loss[QQ];
__device__ float g_perp[QQ];

// ---------------------------------------------------------------------------
// init: zero hist + loss (required every launch; graph replays)
// ---------------------------------------------------------------------------
__global__ void init_kernel() {
    int t = threadIdx.x;
    if (t < CC) g_hist[t] = 0;
    if (t < QQ) g_loss[t] = 0.0f;
}

// ---------------------------------------------------------------------------
// transpose in: x (N, D, T) -> g_res (NT, D), row = n*T + t
// ---------------------------------------------------------------------------
__global__ void transpose_in_kernel(const float* __restrict__ x) {
    __shared__ float tile[32][33];
    int n  = blockIdx.z;
    int t0 = blockIdx.x * 32;
    int d0 = blockIdx.y * 32;
    int tx = threadIdx.x, ty = threadIdx.y;  // (32, 8)

    #pragma unroll
    for (int i = 0; i < 4; i++) {
        int d = d0 + ty + i * 8;
        tile[ty + i * 8][tx] = x[(size_t)n * DD * TT + (size_t)d * TT + (t0 + tx)];
    }
    __syncthreads();
    #pragma unroll
    for (int i = 0; i < 4; i++) {
        int t = t0 + ty + i * 8;
        g_res[(size_t)(n * TT + t) * DD + (d0 + tx)] = tile[tx][ty + i * 8];
    }
}

// ---------------------------------------------------------------------------
// codebook norms: one block per code (all 6 stages at once)
// ---------------------------------------------------------------------------
__global__ void cbnorm_kernel(const float* __restrict__ cb) {
    int code = blockIdx.x;             // 0..6143 (q*1024+c)
    int tid  = threadIdx.x;            // 128
    const float4* cv = (const float4*)(cb + (size_t)code * DD);
    float4 v = cv[tid];
    float s = v.x * v.x + v.y * v.y + v.z * v.z + v.w * v.w;
    #pragma unroll
    for (int off = 16; off > 0; off >>= 1) s += __shfl_down_sync(0xffffffffu, s, off);
    __shared__ float ws[4];
    if ((tid & 31) == 0) ws[tid >> 5] = s;
    __syncthreads();
    if (tid == 0) g_cbnorm[code] = ws[0] + ws[1] + ws[2] + ws[3];
}

// ---------------------------------------------------------------------------
// argmin GEMM: per row of g_res find argmin_c (||c||^2 - 2 r.c) over 1024 codes
// Tile: 64 rows x 128 codes per CTA, 128 threads, 8x8 micro-tile, TK=16,
// double-buffered smem, LDS.128 loads.
// ---------------------------------------------------------------------------
#define TM 64
#define TC 128
#define TK 16
#define NKT (DD / TK)   // 32

__global__ void __launch_bounds__(128) argmin_kernel(const float* __restrict__ cb, int q) {
    __shared__ float As[2][TK][TM];   // 2 * 4KB
    __shared__ float Bs[2][TK][TC];   // 2 * 8KB

    const int tid = threadIdx.x;
    const int tx = tid & 15;          // code group 0..15 (8 codes each)
    const int ty = tid >> 4;          // row group 0..7  (8 rows each)
    const int rowBase = blockIdx.x * TM;
    const float* norms = g_cbnorm + q * CC;

    float bestV[8];
    int   bestI[8];
    #pragma unroll
    for (int i = 0; i < 8; i++) { bestV[i] = 3.4e38f; bestI[i] = 0; }

    const int rA = tid >> 2;          // row for A loads (0..31)
    const int qA = tid & 3;           // quad for A loads
    const int cB = tid >> 2;          // code for B loads (0..31)
    const int qB = tid & 3;

    for (int ct = 0; ct < CC; ct += TC) {
        float acc[8][8];
        #pragma unroll
        for (int i = 0; i < 8; i++)
            #pragma unroll
            for (int j = 0; j < 8; j++) acc[i][j] = 0.0f;

        // ---- prologue: load k-tile 0 into buffer 0 ----
        {
            #pragma unroll
            for (int r = 0; r < 2; r++) {
                int row = rA + r * 32;
                float4 f = *(const float4*)(g_res + (size_t)(rowBase + row) * DD + qA * 4);
                As[0][qA * 4 + 0][row] = f.x; As[0][qA * 4 + 1][row] = f.y;
                As[0][qA * 4 + 2][row] = f.z; As[0][qA * 4 + 3][row] = f.w;
            }
            #pragma unroll
            for (int r = 0; r < 4; r++) {
                int code = cB + r * 32;
                float4 f = *(const float4*)(cb + (size_t)(ct + code) * DD + qB * 4);
                Bs[0][qB * 4 + 0][code] = f.x; Bs[0][qB * 4 + 1][code] = f.y;
                Bs[0][qB * 4 + 2][code] = f.z; Bs[0][qB * 4 + 3][code] = f.w;
            }
        }
        __syncthreads();

        int buf = 0;
        for (int kt = 0; kt < NKT; kt++) {
            // ---- prefetch next k-tile into registers ----
            float4 pa[2], pb[4];
            const bool more = (kt + 1) < NKT;
            if (more) {
                int k0n = (kt + 1) * TK;
                #pragma unroll
                for (int r = 0; r < 2; r++) {
                    int row = rA + r * 32;
                    pa[r] = *(const float4*)(g_res + (size_t)(rowBase + row) * DD + k0n + qA * 4);
                }
                #pragma unroll
                for (int r = 0; r < 4; r++) {
                    int code = cB + r * 32;
                    pb[r] = *(const float4*)(cb + (size_t)(ct + code) * DD + k0n + qB * 4);
                }
            }

            // ---- compute on current buffer ----
            #pragma unroll
            for (int k = 0; k < TK; k++) {
                float4 a0 = *(const float4*)&As[buf][k][ty * 8];
                float4 a1 = *(const float4*)&As[buf][k][ty * 8 + 4];
                float4 b0 = *(const float4*)&Bs[buf][k][tx * 8];
                float4 b1 = *(const float4*)&Bs[buf][k][tx * 8 + 4];
                float a[8] = {a0.x, a0.y, a0.z, a0.w, a1.x, a1.y, a1.z, a1.w};
                float b[8] = {b0.x, b0.y, b0.z, b0.w, b1.x, b1.y, b1.z, b1.w};
                #pragma unroll
                for (int i = 0; i < 8; i++)
                    #pragma unroll
                    for (int j = 0; j < 8; j++)
                        acc[i][j] = fmaf(a[i], b[j], acc[i][j]);
            }

            // ---- store prefetched tile into the other buffer ----
            if (more) {
                int nb = buf ^ 1;
                #pragma unroll
                for (int r = 0; r < 2; r++) {
                    int row = rA + r * 32;
                    As[nb][qA * 4 + 0][row] = pa[r].x; As[nb][qA * 4 + 1][row] = pa[r].y;
                    As[nb][qA * 4 + 2][row] = pa[r].z; As[nb][qA * 4 + 3][row] = pa[r].w;
                }
                #pragma unroll
                for (int r = 0; r < 4; r++) {
                    int code = cB + r * 32;
                    Bs[nb][qB * 4 + 0][code] = pb[r].x; Bs[nb][qB * 4 + 1][code] = pb[r].y;
                    Bs[nb][qB * 4 + 2][code] = pb[r].z; Bs[nb][qB * 4 + 3][code] = pb[r].w;
                }
                __syncthreads();
                buf = nb;
            }
        }

        // ---- distances for this code tile (ascending order -> first-min) ----
        #pragma unroll
        for (int j = 0; j < 8; j++) {
            int c = ct + tx * 8 + j;
            float nc = norms[c];
            #pragma unroll
            for (int i = 0; i < 8; i++) {
                float d = nc - 2.0f * acc[i][j];
                if (d < bestV[i]) { bestV[i] = d; bestI[i] = c; }
            }
        }
        __syncthreads();   // protect smem before next ct prologue
    }

    // reduce across the 16 code-lanes sharing each row (contiguous in warp)
    #pragma unroll
    for (int i = 0; i < 8; i++) {
        float v = bestV[i];
        int   b = bestI[i];
        #pragma unroll
        for (int off = 8; off > 0; off >>= 1) {
            float ov = __shfl_down_sync(0xffffffffu, v, off, 16);
            int   ob = __shfl_down_sync(0xffffffffu, b, off, 16);
            if (ov < v || (ov == v && ob < b)) { v = ov; b = ob; }
        }
        if (tx == 0) {
            int row = rowBase + ty * 8 + i;
            g_indices[row * QQ + q] = b;
            atomicAdd(&g_hist[b], 1);
        }
    }
}

// ---------------------------------------------------------------------------
// residual update + commitment loss: res -= cb[idx]; loss += sum(res_new^2)
// ---------------------------------------------------------------------------
__global__ void update_kernel(const float* __restrict__ cb, int q) {
    int row = blockIdx.x;
    int tid = threadIdx.x;  // 128
    int c = g_indices[row * QQ + q];
    const float4* cv = (const float4*)(cb + (size_t)c * DD);
    float4* rv = (float4*)(g_res + (size_t)row * DD);
    float4 r = rv[tid], v = cv[tid];
    r.x -= v.x; r.y -= v.y; r.z -= v.z; r.w -= v.w;
    rv[tid] = r;
    float s = r.x * r.x + r.y * r.y + r.z * r.z + r.w * r.w;
    #pragma unroll
    for (int off = 16; off > 0; off >>= 1) s += __shfl_down_sync(0xffffffffu, s, off);
    __shared__ float ws[4];
    if ((tid & 31) == 0) ws[tid >> 5] = s;
    __syncthreads();
    if (tid == 0) atomicAdd(&g_loss[q], ws[0] + ws[1] + ws[2] + ws[3]);
}

// ---------------------------------------------------------------------------
// perplexity from histogram; zero histogram for next stage
// ---------------------------------------------------------------------------
__global__ void perp_kernel(int q) {
    int tid = threadIdx.x;  // 256
    float s = 0.0f;
    #pragma unroll
    for (int i = tid; i < CC; i += 256) {
        float p = (float)g_hist[i] * (1.0f / (float)NT);
        s += p * logf(p + 1e-10f);
        g_hist[i] = 0;
    }
    #pragma unroll
    for (int off = 16; off > 0; off >>= 1) s += __shfl_down_sync(0xffffffffu, s, off);
    __shared__ float ws[8];
    if ((tid & 31) == 0) ws[tid >> 5] = s;
    __syncthreads();
    if (tid == 0) {
        float t = 0.0f;
        #pragma unroll
        for (int i = 0; i < 8; i++) t += ws[i];
        g_perp[q] = expf(-t);
    }
}

// ---------------------------------------------------------------------------
// output: quantized_out (N,D,T) = x - residual_final  (transpose back)
// ---------------------------------------------------------------------------
__global__ void transpose_out_kernel(const float* __restrict__ x, float* __restrict__ out) {
    __shared__ float tile[32][33];
    int n  = blockIdx.z;
    int t0 = blockIdx.x * 32;
    int d0 = blockIdx.y * 32;
    int tx = threadIdx.x, ty = threadIdx.y;  // (32, 8)

    #pragma unroll
    for (int i = 0; i < 4; i++) {
        int t = t0 + ty + i * 8;
        tile[ty + i * 8][tx] = g_res[(size_t)(n * TT + t) * DD + (d0 + tx)];
    }
    __syncthreads();
    #pragma unroll
    for (int i = 0; i < 4; i++) {
        int d = d0 + ty + i * 8;
        size_t gi = (size_t)n * DD * TT + (size_t)d * TT + (t0 + tx);
        out[gi] = x[gi] - tile[tx][ty + i * 8];
    }
}

__global__ void idx_kernel(float* __restrict__ out) {
    int i = blockIdx.x * blockDim.x + threadIdx.x;
    if (i < OUT_IDX) out[OUT_QUANT + i] = (float)g_indices[i];
}

__global__ void finalize_kernel(float* __restrict__ out) {
    float l = 0.0f, p = 0.0f;
    #pragma unroll
    for (int q = 0; q < QQ; q++) { l += g_loss[q]; p += g_perp[q]; }
    l = l / ((float)NT * (float)DD) / (float)QQ;
    p = p / (float)QQ;
    out[OUT_QUANT + OUT_IDX + 0] = l;
    out[OUT_QUANT + OUT_IDX + 1] = p;
}

// ---------------------------------------------------------------------------
extern "C" void kernel_launch(void* const* d_in, const int* in_sizes, int n_in,
                              void* d_out, int out_size) {
    const float* x  = (const float*)d_in[0];   // (64, 512, 256) fp32
    const float* cb = (const float*)d_in[1];   // (6, 1024, 512) fp32
    float* out = (float*)d_out;

    init_kernel<<<1, 1024>>>();

    dim3 tb(32, 8);
    dim3 tg(TT / 32, DD / 32, NN);   // (8, 16, 64)
    transpose_in_kernel<<<tg, tb>>>(x);

    cbnorm_kernel<<<QQ * CC, 128>>>(cb);

    for (int q = 0; q < QQ; q++) {
        const float* cbq = cb + (size_t)q * CC * DD;
        argmin_kernel<<<NT / TM, 128>>>(cbq, q);
        update_kernel<<<NT, 128>>>(cbq, q);
        perp_kernel<<<1, 256>>>(q);
    }

    transpose_out_kernel<<<tg, tb>>>(x, out);
    idx_kernel<<<(OUT_IDX + 255) / 256, 256>>>(out);
    finalize_kernel<<<1, 1>>>(out);
}

// round 3
// speedup vs baseline: 1.8469x; 1.1443x over previous
#include <cuda_runtime.h>
#include <cstdint>

// Problem constants
#define NN   64
#define DD   512
#define TT   256
#define QQ   6
#define CC   1024
#define NT   (NN*TT)              // 16384
#define OUT_QUANT   (NN*DD*TT)    // 8388608
#define OUT_IDX     (NT*QQ)       // 98304

// Scratch (device globals — no runtime allocation allowed)
__device__ float g_res[(size_t)NT * DD];               // residual, flat (NT, D)
__device__ float g_cbnorm[QQ * CC];                    // ||c||^2 per code per stage
__device__ int   g_indices[NT * QQ];                   // (N,T,Q) flattened
__device__ unsigned long long g_best[NT];              // packed (dist,code) argmin
__device__ int   g_hist[CC];
__device__ float g_loss[QQ];
__device__ float g_perp[QQ];

// ---------------------------------------------------------------------------
// init: zero hist + loss (required every launch; graph replays)
// ---------------------------------------------------------------------------
__global__ void init_kernel() {
    int t = threadIdx.x;
    if (t < CC) g_hist[t] = 0;
    if (t < QQ) g_loss[t] = 0.0f;
}

// per-stage: reset packed argmin array
__global__ void init_best_kernel() {
    int i = blockIdx.x * blockDim.x + threadIdx.x;
    if (i < NT) g_best[i] = 0xFFFFFFFFFFFFFFFFull;
}

// ---------------------------------------------------------------------------
// transpose in: x (N, D, T) -> g_res (NT, D), row = n*T + t
// ---------------------------------------------------------------------------
__global__ void transpose_in_kernel(const float* __restrict__ x) {
    __shared__ float tile[32][33];
    int n  = blockIdx.z;
    int t0 = blockIdx.x * 32;
    int d0 = blockIdx.y * 32;
    int tx = threadIdx.x, ty = threadIdx.y;  // (32, 8)

    #pragma unroll
    for (int i = 0; i < 4; i++) {
        int d = d0 + ty + i * 8;
        tile[ty + i * 8][tx] = x[(size_t)n * DD * TT + (size_t)d * TT + (t0 + tx)];
    }
    __syncthreads();
    #pragma unroll
    for (int i = 0; i < 4; i++) {
        int t = t0 + ty + i * 8;
        g_res[(size_t)(n * TT + t) * DD + (d0 + tx)] = tile[tx][ty + i * 8];
    }
}

// ---------------------------------------------------------------------------
// codebook norms: one block per code (all 6 stages at once)
// ---------------------------------------------------------------------------
__global__ void cbnorm_kernel(const float* __restrict__ cb) {
    int code = blockIdx.x;             // 0..6143 (q*1024+c)
    int tid  = threadIdx.x;            // 128
    const float4* cv = (const float4*)(cb + (size_t)code * DD);
    float4 v = cv[tid];
    float s = v.x * v.x + v.y * v.y + v.z * v.z + v.w * v.w;
    #pragma unroll
    for (int off = 16; off > 0; off >>= 1) s += __shfl_down_sync(0xffffffffu, s, off);
    __shared__ float ws[4];
    if ((tid & 31) == 0) ws[tid >> 5] = s;
    __syncthreads();
    if (tid == 0) g_cbnorm[code] = ws[0] + ws[1] + ws[2] + ws[3];
}

// ---------------------------------------------------------------------------
// argmin GEMM: grid = (NT/64 row tiles, 8 code slices).
// Each CTA: 64 rows x 128 codes x 512 K; 128 threads; 8x8 micro-tile;
// TK=16 double-buffered smem; LDS.128 loads; packed atomicMin merge.
// ---------------------------------------------------------------------------
#define TM 64
#define TC 128
#define TK 16
#define NKT (DD / TK)   // 32
#define NSLICE (CC / TC) // 8

__device__ __forceinline__ unsigned int sortable_f32(float f) {
    unsigned int u = __float_as_uint(f);
    return (u & 0x80000000u) ? ~u : (u | 0x80000000u);
}

__global__ void __launch_bounds__(128) argmin_kernel(const float* __restrict__ cb, int q) {
    __shared__ float As[2][TK][TM];   // 2 * 4KB
    __shared__ float Bs[2][TK][TC];   // 2 * 8KB

    const int tid = threadIdx.x;
    const int tx = tid & 15;          // code group 0..15 (8 codes each)
    const int ty = tid >> 4;          // row group 0..7  (8 rows each)
    const int rowBase = blockIdx.x * TM;
    const int ct = blockIdx.y * TC;   // code slice base
    const float* norms = g_cbnorm + q * CC;
    const float* cbs = cb + (size_t)ct * DD;

    const int rA = tid >> 2;          // row for A loads (0..31)
    const int qA = tid & 3;           // quad for A loads
    const int cB = tid >> 2;          // code for B loads (0..31)
    const int qB = tid & 3;

    float acc[8][8];
    #pragma unroll
    for (int i = 0; i < 8; i++)
        #pragma unroll
        for (int j = 0; j < 8; j++) acc[i][j] = 0.0f;

    // ---- prologue: load k-tile 0 into buffer 0 ----
    #pragma unroll
    for (int r = 0; r < 2; r++) {
        int row = rA + r * 32;
        float4 f = *(const float4*)(g_res + (size_t)(rowBase + row) * DD + qA * 4);
        As[0][qA * 4 + 0][row] = f.x; As[0][qA * 4 + 1][row] = f.y;
        As[0][qA * 4 + 2][row] = f.z; As[0][qA * 4 + 3][row] = f.w;
    }
    #pragma unroll
    for (int r = 0; r < 4; r++) {
        int code = cB + r * 32;
        float4 f = *(const float4*)(cbs + (size_t)code * DD + qB * 4);
        Bs[0][qB * 4 + 0][code] = f.x; Bs[0][qB * 4 + 1][code] = f.y;
        Bs[0][qB * 4 + 2][code] = f.z; Bs[0][qB * 4 + 3][code] = f.w;
    }
    __syncthreads();

    int buf = 0;
    for (int kt = 0; kt < NKT; kt++) {
        // ---- prefetch next k-tile into registers ----
        float4 pa[2], pb[4];
        const bool more = (kt + 1) < NKT;
        if (more) {
            int k0n = (kt + 1) * TK;
            #pragma unroll
            for (int r = 0; r < 2; r++) {
                int row = rA + r * 32;
                pa[r] = *(const float4*)(g_res + (size_t)(rowBase + row) * DD + k0n + qA * 4);
            }
            #pragma unroll
            for (int r = 0; r < 4; r++) {
                int code = cB + r * 32;
                pb[r] = *(const float4*)(cbs + (size_t)code * DD + k0n + qB * 4);
            }
        }

        // ---- compute on current buffer ----
        #pragma unroll
        for (int k = 0; k < TK; k++) {
            float4 a0 = *(const float4*)&As[buf][k][ty * 8];
            float4 a1 = *(const float4*)&As[buf][k][ty * 8 + 4];
            float4 b0 = *(const float4*)&Bs[buf][k][tx * 8];
            float4 b1 = *(const float4*)&Bs[buf][k][tx * 8 + 4];
            float a[8] = {a0.x, a0.y, a0.z, a0.w, a1.x, a1.y, a1.z, a1.w};
            float b[8] = {b0.x, b0.y, b0.z, b0.w, b1.x, b1.y, b1.z, b1.w};
            #pragma unroll
            for (int i = 0; i < 8; i++)
                #pragma unroll
                for (int j = 0; j < 8; j++)
                    acc[i][j] = fmaf(a[i], b[j], acc[i][j]);
        }

        // ---- store prefetched tile into the other buffer ----
        if (more) {
            int nb = buf ^ 1;
            #pragma unroll
            for (int r = 0; r < 2; r++) {
                int row = rA + r * 32;
                As[nb][qA * 4 + 0][row] = pa[r].x; As[nb][qA * 4 + 1][row] = pa[r].y;
                As[nb][qA * 4 + 2][row] = pa[r].z; As[nb][qA * 4 + 3][row] = pa[r].w;
            }
            #pragma unroll
            for (int r = 0; r < 4; r++) {
                int code = cB + r * 32;
                Bs[nb][qB * 4 + 0][code] = pb[r].x; Bs[nb][qB * 4 + 1][code] = pb[r].y;
                Bs[nb][qB * 4 + 2][code] = pb[r].z; Bs[nb][qB * 4 + 3][code] = pb[r].w;
            }
            __syncthreads();
            buf = nb;
        }
    }

    // ---- per-thread argmin over its 8 codes (ascending -> first-min) ----
    float bestV[8];
    int   bestI[8];
    #pragma unroll
    for (int i = 0; i < 8; i++) { bestV[i] = 3.4e38f; bestI[i] = 0; }
    #pragma unroll
    for (int j = 0; j < 8; j++) {
        int c = ct + tx * 8 + j;
        float nc = norms[c];
        #pragma unroll
        for (int i = 0; i < 8; i++) {
            float d = nc - 2.0f * acc[i][j];
            if (d < bestV[i]) { bestV[i] = d; bestI[i] = c; }
        }
    }

    // reduce across the 16 code-lanes sharing each row, then merge globally
    #pragma unroll
    for (int i = 0; i < 8; i++) {
        float v = bestV[i];
        int   b = bestI[i];
        #pragma unroll
        for (int off = 8; off > 0; off >>= 1) {
            float ov = __shfl_down_sync(0xffffffffu, v, off, 16);
            int   ob = __shfl_down_sync(0xffffffffu, b, off, 16);
            if (ov < v || (ov == v && ob < b)) { v = ov; b = ob; }
        }
        if (tx == 0) {
            int row = rowBase + ty * 8 + i;
            unsigned long long key =
                ((unsigned long long)sortable_f32(v) << 32) | (unsigned int)b;
            atomicMin(&g_best[row], key);
        }
    }
}

// ---------------------------------------------------------------------------
// residual update + commitment loss + index extract + histogram
// ---------------------------------------------------------------------------
__global__ void update_kernel(const float* __restrict__ cb, int q) {
    int row = blockIdx.x;
    int tid = threadIdx.x;  // 128
    int c = (int)(unsigned int)(g_best[row] & 0xFFFFFFFFull);
    if (tid == 0) {
        g_indices[row * QQ + q] = c;
        atomicAdd(&g_hist[c], 1);
    }
    const float4* cv = (const float4*)(cb + (size_t)c * DD);
    float4* rv = (float4*)(g_res + (size_t)row * DD);
    float4 r = rv[tid], v = cv[tid];
    r.x -= v.x; r.y -= v.y; r.z -= v.z; r.w -= v.w;
    rv[tid] = r;
    float s = r.x * r.x + r.y * r.y + r.z * r.z + r.w * r.w;
    #pragma unroll
    for (int off = 16; off > 0; off >>= 1) s += __shfl_down_sync(0xffffffffu, s, off);
    __shared__ float ws[4];
    if ((tid & 31) == 0) ws[tid >> 5] = s;
    __syncthreads();
    if (tid == 0) atomicAdd(&g_loss[q], ws[0] + ws[1] + ws[2] + ws[3]);
}

// ---------------------------------------------------------------------------
// perplexity from histogram; zero histogram for next stage
// ---------------------------------------------------------------------------
__global__ void perp_kernel(int q) {
    int tid = threadIdx.x;  // 256
    float s = 0.0f;
    #pragma unroll
    for (int i = tid; i < CC; i += 256) {
        float p = (float)g_hist[i] * (1.0f / (float)NT);
        s += p * logf(p + 1e-10f);
        g_hist[i] = 0;
    }
    #pragma unroll
    for (int off = 16; off > 0; off >>= 1) s += __shfl_down_sync(0xffffffffu, s, off);
    __shared__ float ws[8];
    if ((tid & 31) == 0) ws[tid >> 5] = s;
    __syncthreads();
    if (tid == 0) {
        float t = 0.0f;
        #pragma unroll
        for (int i = 0; i < 8; i++) t += ws[i];
        g_perp[q] = expf(-t);
    }
}

// ---------------------------------------------------------------------------
// output: quantized_out (N,D,T) = x - residual_final  (transpose back)
// ---------------------------------------------------------------------------
__global__ void transpose_out_kernel(const float* __restrict__ x, float* __restrict__ out) {
    __shared__ float tile[32][33];
    int n  = blockIdx.z;
    int t0 = blockIdx.x * 32;
    int d0 = blockIdx.y * 32;
    int tx = threadIdx.x, ty = threadIdx.y;  // (32, 8)

    #pragma unroll
    for (int i = 0; i < 4; i++) {
        int t = t0 + ty + i * 8;
        tile[ty + i * 8][tx] = g_res[(size_t)(n * TT + t) * DD + (d0 + tx)];
    }
    __syncthreads();
    #pragma unroll
    for (int i = 0; i < 4; i++) {
        int d = d0 + ty + i * 8;
        size_t gi = (size_t)n * DD * TT + (size_t)d * TT + (t0 + tx);
        out[gi] = x[gi] - tile[tx][ty + i * 8];
    }
}

__global__ void idx_kernel(float* __restrict__ out) {
    int i = blockIdx.x * blockDim.x + threadIdx.x;
    if (i < OUT_IDX) out[OUT_QUANT + i] = (float)g_indices[i];
}

__global__ void finalize_kernel(float* __restrict__ out) {
    float l = 0.0f, p = 0.0f;
    #pragma unroll
    for (int q = 0; q < QQ; q++) { l += g_loss[q]; p += g_perp[q]; }
    l = l / ((float)NT * (float)DD) / (float)QQ;
    p = p / (float)QQ;
    out[OUT_QUANT + OUT_IDX + 0] = l;
    out[OUT_QUANT + OUT_IDX + 1] = p;
}

// ---------------------------------------------------------------------------
extern "C" void kernel_launch(void* const* d_in, const int* in_sizes, int n_in,
                              void* d_out, int out_size) {
    const float* x  = (const float*)d_in[0];   // (64, 512, 256) fp32
    const float* cb = (const float*)d_in[1];   // (6, 1024, 512) fp32
    float* out = (float*)d_out;

    init_kernel<<<1, 1024>>>();

    dim3 tb(32, 8);
    dim3 tg(TT / 32, DD / 32, NN);   // (8, 16, 64)
    transpose_in_kernel<<<tg, tb>>>(x);

    cbnorm_kernel<<<QQ * CC, 128>>>(cb);

    for (int q = 0; q < QQ; q++) {
        const float* cbq = cb + (size_t)q * CC * DD;
        init_best_kernel<<<NT / 256, 256>>>();
        dim3 ag(NT / TM, NSLICE);    // (256, 8) = 2048 CTAs
        argmin_kernel<<<ag, 128>>>(cbq, q);
        update_kernel<<<NT, 128>>>(cbq, q);
        perp_kernel<<<1, 256>>>(q);
    }

    transpose_out_kernel<<<tg, tb>>>(x, out);
    idx_kernel<<<(OUT_IDX + 255) / 256, 256>>>(out);
    finalize_kernel<<<1, 1>>>(out);
}

// round 5
// speedup vs baseline: 4.8300x; 2.6151x over previous
#include <cuda_runtime.h>
#include <cuda_fp16.h>
#include <cstdint>

// Problem constants
#define NN   64
#define DD   512
#define TT   256
#define QQ   6
#define CC   1024
#define NT   (NN*TT)              // 16384
#define OUT_QUANT   (NN*DD*TT)    // 8388608
#define OUT_IDX     (NT*QQ)       // 98304

// Scratch (device globals — no runtime allocation allowed)
__device__ float  g_res[(size_t)NT * DD];       // residual fp32, flat (NT, D)
__device__ __half g_res_h[(size_t)NT * DD];     // residual hi (fp16)
__device__ __half g_res_l[(size_t)NT * DD];     // residual lo (fp16)
__device__ __half g_cb_h[(size_t)QQ * CC * DD]; // codebook hi
__device__ __half g_cb_l[(size_t)QQ * CC * DD]; // codebook lo
__device__ float  g_cbnorm[QQ * CC];            // ||c||^2 per code per stage
__device__ int    g_indices[NT * QQ];
__device__ unsigned long long g_best[NT];       // packed (dist,code)
__device__ int    g_hist[CC];
__device__ float  g_loss[QQ];
__device__ float  g_perp[QQ];

// ===========================================================================
// helpers
// ===========================================================================
__device__ __forceinline__ uint32_t smem_u32(const void* p) {
    uint32_t a;
    asm("{ .reg .u64 t; cvta.to.shared.u64 t, %1; cvt.u32.u64 %0, t; }" : "=r"(a) : "l"(p));
    return a;
}
__device__ __forceinline__ uint32_t swz(uint32_t off) {           // Swizzle<3,4,3>
    return off ^ ((off >> 3) & 0x70);
}
__device__ __forceinline__ unsigned int sortable_f32(float f) {
    unsigned int u = __float_as_uint(f);
    return (u & 0x80000000u) ? ~u : (u | 0x80000000u);
}

#define CP16(dst, src) \
    asm volatile("cp.async.ca.shared.global [%0], [%1], 16;" :: "r"(dst), "l"(src))
#define CP_COMMIT() asm volatile("cp.async.commit_group;" ::: "memory")
#define CP_WAIT1()  asm volatile("cp.async.wait_group 1;" ::: "memory")
#define CP_WAIT0()  asm volatile("cp.async.wait_group 0;" ::: "memory")

__device__ __forceinline__ void ldsm_x4(uint32_t* r, uint32_t addr) {
    asm volatile("ldmatrix.sync.aligned.m8n8.x4.shared.b16 {%0,%1,%2,%3}, [%4];"
        : "=r"(r[0]), "=r"(r[1]), "=r"(r[2]), "=r"(r[3]) : "r"(addr));
}
__device__ __forceinline__ void mma_16816(float* d, const uint32_t* a,
                                          uint32_t b0, uint32_t b1) {
    asm volatile(
        "mma.sync.aligned.m16n8k16.row.col.f32.f16.f16.f32 "
        "{%0,%1,%2,%3}, {%4,%5,%6,%7}, {%8,%9}, {%0,%1,%2,%3};"
        : "+f"(d[0]), "+f"(d[1]), "+f"(d[2]), "+f"(d[3])
        : "r"(a[0]), "r"(a[1]), "r"(a[2]), "r"(a[3]), "r"(b0), "r"(b1));
}

// ===========================================================================
// small kernels
// ===========================================================================
__global__ void init_kernel() {
    int t = threadIdx.x;
    if (t < CC) g_hist[t] = 0;
    if (t < QQ) g_loss[t] = 0.0f;
}
__global__ void init_best_kernel() {
    int i = blockIdx.x * blockDim.x + threadIdx.x;
    if (i < NT) g_best[i] = 0xFFFFFFFFFFFFFFFFull;
}
__global__ void cbsplit_kernel(const float* __restrict__ cb) {
    size_t i = (size_t)blockIdx.x * blockDim.x + threadIdx.x;  // < QQ*CC*DD
    float v = cb[i];
    __half h = __float2half(v);
    g_cb_h[i] = h;
    g_cb_l[i] = __float2half(v - __half2float(h));
}

// transpose in: x (N, D, T) -> g_res (NT, D) + fp16 hi/lo
__global__ void transpose_in_kernel(const float* __restrict__ x) {
    __shared__ float tile[32][33];
    int n  = blockIdx.z;
    int t0 = blockIdx.x * 32;
    int d0 = blockIdx.y * 32;
    int tx = threadIdx.x, ty = threadIdx.y;  // (32, 8)

    #pragma unroll
    for (int i = 0; i < 4; i++) {
        int d = d0 + ty + i * 8;
        tile[ty + i * 8][tx] = x[(size_t)n * DD * TT + (size_t)d * TT + (t0 + tx)];
    }
    __syncthreads();
    #pragma unroll
    for (int i = 0; i < 4; i++) {
        int t = t0 + ty + i * 8;
        float v = tile[tx][ty + i * 8];
        size_t gi = (size_t)(n * TT + t) * DD + (d0 + tx);
        g_res[gi] = v;
        __half h = __float2half(v);
        g_res_h[gi] = h;
        g_res_l[gi] = __float2half(v - __half2float(h));
    }
}

__global__ void cbnorm_kernel(const float* __restrict__ cb) {
    int code = blockIdx.x;             // 0..6143
    int tid  = threadIdx.x;            // 128
    const float4* cv = (const float4*)(cb + (size_t)code * DD);
    float4 v = cv[tid];
    float s = v.x * v.x + v.y * v.y + v.z * v.z + v.w * v.w;
    #pragma unroll
    for (int off = 16; off > 0; off >>= 1) s += __shfl_down_sync(0xffffffffu, s, off);
    __shared__ float ws[4];
    if ((tid & 31) == 0) ws[tid >> 5] = s;
    __syncthreads();
    if (tid == 0) g_cbnorm[code] = ws[0] + ws[1] + ws[2] + ws[3];
}

// ===========================================================================
// mma.sync argmin: grid (NT/64, CC/128). CTA: 64 rows x 128 codes x K512.
// 256 threads = 8 warps (2m x 4n), warp tile 32x32 (2x4 m16n8k16 frags).
// fp16 2-split: dot = hh + hl + lh, fp32 accum. cp.async double buffer.
// ===========================================================================
#define MROWS   64
#define NCODES  128
#define KC      64                  // halves per chunk (128 B rows)
#define NCHUNK  (DD / KC)           // 8

// dynamic smem layout
#define OFF_BEST 0                  // 64 * 8 B
#define OFF_BUF  1024
#define OFF_AH   0
#define OFF_AL   (8*1024)
#define OFF_BH   (16*1024)
#define OFF_BL   (32*1024)
#define BUF_BYTES (48*1024)
#define ARG_SMEM (OFF_BUF + 2*BUF_BYTES)   // 99328

__global__ void __launch_bounds__(256) argmin_kernel(int q) {
    extern __shared__ char smem[];
    unsigned long long* s_best = (unsigned long long*)smem;
    const uint32_t sb = smem_u32(smem);
    const int tid  = threadIdx.x;
    const int lane = tid & 31;
    const int wid  = tid >> 5;
    const int wm   = wid & 1;          // 0..1  (32 rows each)
    const int wn   = wid >> 1;         // 0..3  (32 codes each)
    const int rowBase = blockIdx.x * MROWS;
    const int ct      = blockIdx.y * NCODES;

    const __half* __restrict__ resh = g_res_h;
    const __half* __restrict__ resl = g_res_l;
    const __half* __restrict__ cbh  = g_cb_h + (size_t)q * CC * DD;
    const __half* __restrict__ cbl  = g_cb_l + (size_t)q * CC * DD;
    const float*  __restrict__ norms = g_cbnorm + q * CC;

    if (tid < MROWS) s_best[tid] = 0xFFFFFFFFFFFFFFFFull;

    float d[2][4][4];
    #pragma unroll
    for (int i = 0; i < 2; i++)
        #pragma unroll
        for (int j = 0; j < 4; j++)
            #pragma unroll
            for (int e = 0; e < 4; e++) d[i][j][e] = 0.0f;

    // ldmatrix lane-address components
    const int aRow = (lane & 7) + ((lane >> 3) & 1) * 8;
    const int aK   = ((lane >> 4) & 1) * 8;
    const int bCode = (lane & 7) + ((lane >> 4) & 1) * 8;
    const int bK   = ((lane >> 3) & 1) * 8;

    // ---- cp.async chunk issue ----
    auto issue = [&](int c) {
        const uint32_t bufb = sb + OFF_BUF + (c & 1) * BUF_BYTES;
        const int k0 = c * KC;
        #pragma unroll
        for (int p = 0; p < 2; p++) {
            int seg = tid + p * 256;         // 0..511
            int row = seg >> 3, s8 = seg & 7;
            uint32_t so = swz((uint32_t)(row * 128 + s8 * 16));
            const size_t gi = (size_t)(rowBase + row) * DD + k0 + s8 * 8;
            CP16(bufb + OFF_AH + so, resh + gi);
            CP16(bufb + OFF_AL + so, resl + gi);
        }
        #pragma unroll
        for (int p = 0; p < 4; p++) {
            int seg = tid + p * 256;         // 0..1023
            int row = seg >> 3, s8 = seg & 7;
            uint32_t so = swz((uint32_t)(row * 128 + s8 * 16));
            const size_t gi = (size_t)(ct + row) * DD + k0 + s8 * 8;
            CP16(bufb + OFF_BH + so, cbh + gi);
            CP16(bufb + OFF_BL + so, cbl + gi);
        }
        CP_COMMIT();
    };

    issue(0);
    for (int c = 0; c < NCHUNK; c++) {
        if (c + 1 < NCHUNK) { issue(c + 1); CP_WAIT1(); }
        else                { CP_WAIT0(); }
        __syncthreads();

        const uint32_t bufb = sb + OFF_BUF + (c & 1) * BUF_BYTES;
        #pragma unroll
        for (int kk = 0; kk < KC; kk += 16) {
            uint32_t ah[2][4], al[2][4], bh[2][4], bl[2][4];
            #pragma unroll
            for (int i = 0; i < 2; i++) {
                uint32_t so = swz((uint32_t)((wm * 32 + i * 16 + aRow) * 128 + (kk + aK) * 2));
                ldsm_x4(ah[i], bufb + OFF_AH + so);
                ldsm_x4(al[i], bufb + OFF_AL + so);
            }
            #pragma unroll
            for (int j2 = 0; j2 < 2; j2++) {
                uint32_t so = swz((uint32_t)((wn * 32 + j2 * 16 + bCode) * 128 + (kk + bK) * 2));
                ldsm_x4(bh[j2], bufb + OFF_BH + so);
                ldsm_x4(bl[j2], bufb + OFF_BL + so);
            }
            #pragma unroll
            for (int i = 0; i < 2; i++)
                #pragma unroll
                for (int j = 0; j < 4; j++) {
                    const int j2 = j >> 1, o = (j & 1) * 2;
                    mma_16816(d[i][j], ah[i], bh[j2][o], bh[j2][o + 1]);   // hh
                    mma_16816(d[i][j], ah[i], bl[j2][o], bl[j2][o + 1]);   // hl
                    mma_16816(d[i][j], al[i], bh[j2][o], bh[j2][o + 1]);   // lh
                }
        }
        __syncthreads();
    }

    // ---- epilogue: distances + argmin ----
    float bV[4];
    int   bI[4];
    #pragma unroll
    for (int s = 0; s < 4; s++) { bV[s] = 3.4e38f; bI[s] = 0; }

    #pragma unroll
    for (int i = 0; i < 2; i++)
        #pragma unroll
        for (int j = 0; j < 4; j++)
            #pragma unroll
            for (int e = 0; e < 4; e++) {
                int col = ct + wn * 32 + j * 8 + 2 * (lane & 3) + (e & 1);
                float dist = __ldg(&norms[col]) - 2.0f * d[i][j][e];
                int s = i * 2 + (e >> 1);
                if (dist < bV[s]) { bV[s] = dist; bI[s] = col; }
            }

    #pragma unroll
    for (int s = 0; s < 4; s++) {
        float v = bV[s];
        int   b = bI[s];
        #pragma unroll
        for (int off = 1; off < 4; off <<= 1) {
            float ov = __shfl_xor_sync(0xffffffffu, v, off);
            int   ob = __shfl_xor_sync(0xffffffffu, b, off);
            if (ov < v || (ov == v && ob < b)) { v = ov; b = ob; }
        }
        if ((lane & 3) == 0) {
            int rowL = wm * 32 + (s >> 1) * 16 + (lane >> 2) + (s & 1) * 8;
            unsigned long long key =
                ((unsigned long long)sortable_f32(v) << 32) | (unsigned int)b;
            atomicMin(&s_best[rowL], key);
        }
    }
    __syncthreads();
    if (tid < MROWS) atomicMin(&g_best[rowBase + tid], s_best[tid]);
}

// ---------------------------------------------------------------------------
// residual update + commitment loss + fp16 hi/lo refresh + hist/index extract
// ---------------------------------------------------------------------------
__global__ void update_kernel(const float* __restrict__ cb, int q) {
    int row = blockIdx.x;
    int tid = threadIdx.x;  // 128
    int c = (int)(unsigned int)(g_best[row] & 0xFFFFFFFFull);
    if (tid == 0) {
        g_indices[row * QQ + q] = c;
        atomicAdd(&g_hist[c], 1);
    }
    const float4* cv = (const float4*)(cb + (size_t)c * DD);
    float4* rv = (float4*)(g_res + (size_t)row * DD);
    float4 r = rv[tid], v = cv[tid];
    r.x -= v.x; r.y -= v.y; r.z -= v.z; r.w -= v.w;
    rv[tid] = r;

    __half hx = __float2half(r.x), hy = __float2half(r.y);
    __half hz = __float2half(r.z), hw = __float2half(r.w);
    __half lx = __float2half(r.x - __half2float(hx));
    __half ly = __float2half(r.y - __half2float(hy));
    __half lz = __float2half(r.z - __half2float(hz));
    __half lw = __float2half(r.w - __half2float(hw));
    __half2* hp = (__half2*)(g_res_h + (size_t)row * DD + tid * 4);
    __half2* lp = (__half2*)(g_res_l + (size_t)row * DD + tid * 4);
    hp[0] = __halves2half2(hx, hy); hp[1] = __halves2half2(hz, hw);
    lp[0] = __halves2half2(lx, ly); lp[1] = __halves2half2(lz, lw);

    float s = r.x * r.x + r.y * r.y + r.z * r.z + r.w * r.w;
    #pragma unroll
    for (int off = 16; off > 0; off >>= 1) s += __shfl_down_sync(0xffffffffu, s, off);
    __shared__ float ws[4];
    if ((tid & 31) == 0) ws[tid >> 5] = s;
    __syncthreads();
    if (tid == 0) atomicAdd(&g_loss[q], ws[0] + ws[1] + ws[2] + ws[3]);
}

// ---------------------------------------------------------------------------
__global__ void perp_kernel(int q) {
    int tid = threadIdx.x;  // 256
    float s = 0.0f;
    #pragma unroll
    for (int i = tid; i < CC; i += 256) {
        float p = (float)g_hist[i] * (1.0f / (float)NT);
        s += p * logf(p + 1e-10f);
        g_hist[i] = 0;
    }
    #pragma unroll
    for (int off = 16; off > 0; off >>= 1) s += __shfl_down_sync(0xffffffffu, s, off);
    __shared__ float ws[8];
    if ((tid & 31) == 0) ws[tid >> 5] = s;
    __syncthreads();
    if (tid == 0) {
        float t = 0.0f;
        #pragma unroll
        for (int i = 0; i < 8; i++) t += ws[i];
        g_perp[q] = expf(-t);
    }
}

// ---------------------------------------------------------------------------
__global__ void transpose_out_kernel(const float* __restrict__ x, float* __restrict__ out) {
    __shared__ float tile[32][33];
    int n  = blockIdx.z;
    int t0 = blockIdx.x * 32;
    int d0 = blockIdx.y * 32;
    int tx = threadIdx.x, ty = threadIdx.y;  // (32, 8)

    #pragma unroll
    for (int i = 0; i < 4; i++) {
        int t = t0 + ty + i * 8;
        tile[ty + i * 8][tx] = g_res[(size_t)(n * TT + t) * DD + (d0 + tx)];
    }
    __syncthreads();
    #pragma unroll
    for (int i = 0; i < 4; i++) {
        int d = d0 + ty + i * 8;
        size_t gi = (size_t)n * DD * TT + (size_t)d * TT + (t0 + tx);
        out[gi] = x[gi] - tile[tx][ty + i * 8];
    }
}

__global__ void idx_kernel(float* __restrict__ out) {
    int i = blockIdx.x * blockDim.x + threadIdx.x;
    if (i < OUT_IDX) out[OUT_QUANT + i] = (float)g_indices[i];
}

__global__ void finalize_kernel(float* __restrict__ out) {
    float l = 0.0f, p = 0.0f;
    #pragma unroll
    for (int q = 0; q < QQ; q++) { l += g_loss[q]; p += g_perp[q]; }
    l = l / ((float)NT * (float)DD) / (float)QQ;
    p = p / (float)QQ;
    out[OUT_QUANT + OUT_IDX + 0] = l;
    out[OUT_QUANT + OUT_IDX + 1] = p;
}

// ---------------------------------------------------------------------------
extern "C" void kernel_launch(void* const* d_in, const int* in_sizes, int n_in,
                              void* d_out, int out_size) {
    const float* x  = (const float*)d_in[0];   // (64, 512, 256) fp32
    const float* cb = (const float*)d_in[1];   // (6, 1024, 512) fp32
    float* out = (float*)d_out;

    static bool attr_set = false;
    if (!attr_set) {
        cudaFuncSetAttribute(argmin_kernel,
                             cudaFuncAttributeMaxDynamicSharedMemorySize, ARG_SMEM);
        attr_set = true;
    }

    init_kernel<<<1, 1024>>>();

    dim3 tb(32, 8);
    dim3 tg(TT / 32, DD / 32, NN);   // (8, 16, 64)
    transpose_in_kernel<<<tg, tb>>>(x);

    cbsplit_kernel<<<(QQ * CC * DD) / 256, 256>>>(cb);
    cbnorm_kernel<<<QQ * CC, 128>>>(cb);

    for (int q = 0; q < QQ; q++) {
        const float* cbq = cb + (size_t)q * CC * DD;
        init_best_kernel<<<NT / 256, 256>>>();
        dim3 ag(NT / MROWS, CC / NCODES);   // (256, 8)
        argmin_kernel<<<ag, 256, ARG_SMEM>>>(q);
        update_kernel<<<NT, 128>>>(cbq, q);
        perp_kernel<<<1, 256>>>(q);
    }

    transpose_out_kernel<<<tg, tb>>>(x, out);
    idx_kernel<<<(OUT_IDX + 255) / 256, 256>>>(out);
    finalize_kernel<<<1, 1>>>(out);
}

// round 6
// speedup vs baseline: 5.3054x; 1.0984x over previous
#include <cuda_runtime.h>
#include <cuda_fp16.h>
#include <cstdint>

// Problem constants
#define NN   64
#define DD   512
#define TT   256
#define QQ   6
#define CC   1024
#define NT   (NN*TT)              // 16384
#define OUT_QUANT   (NN*DD*TT)    // 8388608
#define OUT_IDX     (NT*QQ)       // 98304

// Scratch (device globals — no runtime allocation allowed)
__device__ __half g_res_h[(size_t)NT * DD];     // residual hi (fp16)
__device__ __half g_res_l[(size_t)NT * DD];     // residual lo (fp16)
__device__ __half g_cb_h[(size_t)QQ * CC * DD]; // codebook hi
__device__ __half g_cb_l[(size_t)QQ * CC * DD]; // codebook lo
__device__ float  g_cbnorm[QQ * CC];            // ||c||^2 per code per stage
__device__ int    g_indices[NT * QQ];
__device__ unsigned long long g_best[NT];       // packed (dist,code)
__device__ int    g_hist2[QQ * CC];             // per-stage histograms
__device__ float  g_loss[QQ];

// ===========================================================================
// helpers
// ===========================================================================
__device__ __forceinline__ uint32_t smem_u32(const void* p) {
    uint32_t a;
    asm("{ .reg .u64 t; cvta.to.shared.u64 t, %1; cvt.u32.u64 %0, t; }" : "=r"(a) : "l"(p));
    return a;
}
__device__ __forceinline__ uint32_t swz(uint32_t off) {           // Swizzle<3,4,3>
    return off ^ ((off >> 3) & 0x70);
}
__device__ __forceinline__ unsigned int sortable_f32(float f) {
    unsigned int u = __float_as_uint(f);
    return (u & 0x80000000u) ? ~u : (u | 0x80000000u);
}

#define CP16(dst, src) \
    asm volatile("cp.async.ca.shared.global [%0], [%1], 16;" :: "r"(dst), "l"(src))
#define CP_COMMIT() asm volatile("cp.async.commit_group;" ::: "memory")
#define CP_WAIT1()  asm volatile("cp.async.wait_group 1;" ::: "memory")
#define CP_WAIT0()  asm volatile("cp.async.wait_group 0;" ::: "memory")

__device__ __forceinline__ void ldsm_x4(uint32_t* r, uint32_t addr) {
    asm volatile("ldmatrix.sync.aligned.m8n8.x4.shared.b16 {%0,%1,%2,%3}, [%4];"
        : "=r"(r[0]), "=r"(r[1]), "=r"(r[2]), "=r"(r[3]) : "r"(addr));
}
__device__ __forceinline__ void mma_16816(float* d, const uint32_t* a,
                                          uint32_t b0, uint32_t b1) {
    asm volatile(
        "mma.sync.aligned.m16n8k16.row.col.f32.f16.f16.f32 "
        "{%0,%1,%2,%3}, {%4,%5,%6,%7}, {%8,%9}, {%0,%1,%2,%3};"
        : "+f"(d[0]), "+f"(d[1]), "+f"(d[2]), "+f"(d[3])
        : "r"(a[0]), "r"(a[1]), "r"(a[2]), "r"(a[3]), "r"(b0), "r"(b1));
}

// ===========================================================================
// init: zero hist2 + loss, set g_best to +inf keys (graph replays)
// ===========================================================================
__global__ void init_kernel() {
    int i = blockIdx.x * blockDim.x + threadIdx.x;   // grid 64 x 256 = 16384
    if (i < NT) g_best[i] = 0xFFFFFFFFFFFFFFFFull;
    if (i < QQ * CC) g_hist2[i] = 0;
    if (i < QQ) g_loss[i] = 0.0f;
}

// codebook prep: split fp32 -> (hi, lo) fp16 AND compute ||c||^2; one block/code
__global__ void cbprep_kernel(const float* __restrict__ cb) {
    int code = blockIdx.x;             // 0..6143 (q*1024+c)
    int tid  = threadIdx.x;            // 128
    size_t base = (size_t)code * DD;
    float4 v = ((const float4*)(cb + base))[tid];

    __half hx = __float2half(v.x), hy = __float2half(v.y);
    __half hz = __float2half(v.z), hw = __float2half(v.w);
    __half2* hp = (__half2*)(g_cb_h + base + tid * 4);
    __half2* lp = (__half2*)(g_cb_l + base + tid * 4);
    hp[0] = __halves2half2(hx, hy); hp[1] = __halves2half2(hz, hw);
    lp[0] = __halves2half2(__float2half(v.x - __half2float(hx)),
                           __float2half(v.y - __half2float(hy)));
    lp[1] = __halves2half2(__float2half(v.z - __half2float(hz)),
                           __float2half(v.w - __half2float(hw)));

    float s = v.x * v.x + v.y * v.y + v.z * v.z + v.w * v.w;
    #pragma unroll
    for (int off = 16; off > 0; off >>= 1) s += __shfl_down_sync(0xffffffffu, s, off);
    __shared__ float ws[4];
    if ((tid & 31) == 0) ws[tid >> 5] = s;
    __syncthreads();
    if (tid == 0) g_cbnorm[code] = ws[0] + ws[1] + ws[2] + ws[3];
}

// transpose in: x (N, D, T) -> residual (NT, D) as fp16 hi/lo
__global__ void transpose_in_kernel(const float* __restrict__ x) {
    __shared__ float tile[32][33];
    int n  = blockIdx.z;
    int t0 = blockIdx.x * 32;
    int d0 = blockIdx.y * 32;
    int tx = threadIdx.x, ty = threadIdx.y;  // (32, 8)

    #pragma unroll
    for (int i = 0; i < 4; i++) {
        int d = d0 + ty + i * 8;
        tile[ty + i * 8][tx] = x[(size_t)n * DD * TT + (size_t)d * TT + (t0 + tx)];
    }
    __syncthreads();
    #pragma unroll
    for (int i = 0; i < 4; i++) {
        int t = t0 + ty + i * 8;
        float v = tile[tx][ty + i * 8];
        size_t gi = (size_t)(n * TT + t) * DD + (d0 + tx);
        __half h = __float2half(v);
        g_res_h[gi] = h;
        g_res_l[gi] = __float2half(v - __half2float(h));
    }
}

// ===========================================================================
// mma.sync argmin: grid (NT/64, CC/128). CTA: 64 rows x 128 codes x K512.
// 256 threads = 8 warps (2m x 4n), warp tile 32x32 (2x4 m16n8k16 frags).
// fp16 2-split: dot = hh + hl + lh, fp32 accum. cp.async double buffer.
// ===========================================================================
#define MROWS   64
#define NCODES  128
#define KC      64                  // halves per chunk (128 B rows)
#define NCHUNK  (DD / KC)           // 8

// dynamic smem layout
#define OFF_BUF  1024
#define OFF_AH   0
#define OFF_AL   (8*1024)
#define OFF_BH   (16*1024)
#define OFF_BL   (32*1024)
#define BUF_BYTES (48*1024)
#define ARG_SMEM (OFF_BUF + 2*BUF_BYTES)   // 99328

__global__ void __launch_bounds__(256) argmin_kernel(int q) {
    extern __shared__ char smem[];
    unsigned long long* s_best = (unsigned long long*)smem;
    const uint32_t sb = smem_u32(smem);
    const int tid  = threadIdx.x;
    const int lane = tid & 31;
    const int wid  = tid >> 5;
    const int wm   = wid & 1;          // 0..1  (32 rows each)
    const int wn   = wid >> 1;         // 0..3  (32 codes each)
    const int rowBase = blockIdx.x * MROWS;
    const int ct      = blockIdx.y * NCODES;

    const __half* __restrict__ resh = g_res_h;
    const __half* __restrict__ resl = g_res_l;
    const __half* __restrict__ cbh  = g_cb_h + (size_t)q * CC * DD;
    const __half* __restrict__ cbl  = g_cb_l + (size_t)q * CC * DD;
    const float*  __restrict__ norms = g_cbnorm + q * CC;

    if (tid < MROWS) s_best[tid] = 0xFFFFFFFFFFFFFFFFull;

    float d[2][4][4];
    #pragma unroll
    for (int i = 0; i < 2; i++)
        #pragma unroll
        for (int j = 0; j < 4; j++)
            #pragma unroll
            for (int e = 0; e < 4; e++) d[i][j][e] = 0.0f;

    // ldmatrix lane-address components
    const int aRow = (lane & 7) + ((lane >> 3) & 1) * 8;
    const int aK   = ((lane >> 4) & 1) * 8;
    const int bCode = (lane & 7) + ((lane >> 4) & 1) * 8;
    const int bK   = ((lane >> 3) & 1) * 8;

    auto issue = [&](int c) {
        const uint32_t bufb = sb + OFF_BUF + (c & 1) * BUF_BYTES;
        const int k0 = c * KC;
        #pragma unroll
        for (int p = 0; p < 2; p++) {
            int seg = tid + p * 256;         // 0..511
            int row = seg >> 3, s8 = seg & 7;
            uint32_t so = swz((uint32_t)(row * 128 + s8 * 16));
            const size_t gi = (size_t)(rowBase + row) * DD + k0 + s8 * 8;
            CP16(bufb + OFF_AH + so, resh + gi);
            CP16(bufb + OFF_AL + so, resl + gi);
        }
        #pragma unroll
        for (int p = 0; p < 4; p++) {
            int seg = tid + p * 256;         // 0..1023
            int row = seg >> 3, s8 = seg & 7;
            uint32_t so = swz((uint32_t)(row * 128 + s8 * 16));
            const size_t gi = (size_t)(ct + row) * DD + k0 + s8 * 8;
            CP16(bufb + OFF_BH + so, cbh + gi);
            CP16(bufb + OFF_BL + so, cbl + gi);
        }
        CP_COMMIT();
    };

    issue(0);
    for (int c = 0; c < NCHUNK; c++) {
        if (c + 1 < NCHUNK) { issue(c + 1); CP_WAIT1(); }
        else                { CP_WAIT0(); }
        __syncthreads();

        const uint32_t bufb = sb + OFF_BUF + (c & 1) * BUF_BYTES;
        #pragma unroll
        for (int kk = 0; kk < KC; kk += 16) {
            uint32_t ah[2][4], al[2][4], bh[2][4], bl[2][4];
            #pragma unroll
            for (int i = 0; i < 2; i++) {
                uint32_t so = swz((uint32_t)((wm * 32 + i * 16 + aRow) * 128 + (kk + aK) * 2));
                ldsm_x4(ah[i], bufb + OFF_AH + so);
                ldsm_x4(al[i], bufb + OFF_AL + so);
            }
            #pragma unroll
            for (int j2 = 0; j2 < 2; j2++) {
                uint32_t so = swz((uint32_t)((wn * 32 + j2 * 16 + bCode) * 128 + (kk + bK) * 2));
                ldsm_x4(bh[j2], bufb + OFF_BH + so);
                ldsm_x4(bl[j2], bufb + OFF_BL + so);
            }
            #pragma unroll
            for (int i = 0; i < 2; i++)
                #pragma unroll
                for (int j = 0; j < 4; j++) {
                    const int j2 = j >> 1, o = (j & 1) * 2;
                    mma_16816(d[i][j], ah[i], bh[j2][o], bh[j2][o + 1]);   // hh
                    mma_16816(d[i][j], ah[i], bl[j2][o], bl[j2][o + 1]);   // hl
                    mma_16816(d[i][j], al[i], bh[j2][o], bh[j2][o + 1]);   // lh
                }
        }
        __syncthreads();
    }

    // ---- epilogue: distances + argmin ----
    float bV[4];
    int   bI[4];
    #pragma unroll
    for (int s = 0; s < 4; s++) { bV[s] = 3.4e38f; bI[s] = 0; }

    #pragma unroll
    for (int i = 0; i < 2; i++)
        #pragma unroll
        for (int j = 0; j < 4; j++)
            #pragma unroll
            for (int e = 0; e < 4; e++) {
                int col = ct + wn * 32 + j * 8 + 2 * (lane & 3) + (e & 1);
                float dist = __ldg(&norms[col]) - 2.0f * d[i][j][e];
                int s = i * 2 + (e >> 1);
                if (dist < bV[s]) { bV[s] = dist; bI[s] = col; }
            }

    #pragma unroll
    for (int s = 0; s < 4; s++) {
        float v = bV[s];
        int   b = bI[s];
        #pragma unroll
        for (int off = 1; off < 4; off <<= 1) {
            float ov = __shfl_xor_sync(0xffffffffu, v, off);
            int   ob = __shfl_xor_sync(0xffffffffu, b, off);
            if (ov < v || (ov == v && ob < b)) { v = ov; b = ob; }
        }
        if ((lane & 3) == 0) {
            int rowL = wm * 32 + (s >> 1) * 16 + (lane >> 2) + (s & 1) * 8;
            unsigned long long key =
                ((unsigned long long)sortable_f32(v) << 32) | (unsigned int)b;
            atomicMin(&s_best[rowL], key);
        }
    }
    __syncthreads();
    if (tid < MROWS) atomicMin(&g_best[rowBase + tid], s_best[tid]);
}

// ===========================================================================
// residual update: res(h,l) -= cb[idx]; commitment loss; histogram; index
// extract; reset g_best for the next stage. 2 rows per block, 256 threads.
// ===========================================================================
__global__ void __launch_bounds__(256) update_kernel(const float* __restrict__ cb, int q) {
    const int tid = threadIdx.x;
    const int sub = tid >> 7;            // row within block (0/1)
    const int t   = tid & 127;           // 128 threads per row
    const int row = blockIdx.x * 2 + sub;

    const int c = (int)(unsigned int)(g_best[row] & 0xFFFFFFFFull);
    __syncthreads();                     // all reads of g_best before reset
    if (t == 0) {
        g_indices[row * QQ + q] = c;
        atomicAdd(&g_hist2[q * CC + c], 1);
        g_best[row] = 0xFFFFFFFFFFFFFFFFull;   // ready for next stage / launch
    }

    const size_t base = (size_t)row * DD + t * 4;
    __half2* hp = (__half2*)(g_res_h + base);
    __half2* lp = (__half2*)(g_res_l + base);
    __half2 h0 = hp[0], h1 = hp[1], l0 = lp[0], l1 = lp[1];
    float4 cv = *(const float4*)(cb + (size_t)c * DD + t * 4);

    float r0 = (__low2float(h0)  + __low2float(l0))  - cv.x;
    float r1 = (__high2float(h0) + __high2float(l0)) - cv.y;
    float r2 = (__low2float(h1)  + __low2float(l1))  - cv.z;
    float r3 = (__high2float(h1) + __high2float(l1)) - cv.w;

    __half a0 = __float2half(r0), a1 = __float2half(r1);
    __half a2 = __float2half(r2), a3 = __float2half(r3);
    hp[0] = __halves2half2(a0, a1);
    hp[1] = __halves2half2(a2, a3);
    lp[0] = __halves2half2(__float2half(r0 - __half2float(a0)),
                           __float2half(r1 - __half2float(a1)));
    lp[1] = __halves2half2(__float2half(r2 - __half2float(a2)),
                           __float2half(r3 - __half2float(a3)));

    float s = r0 * r0 + r1 * r1 + r2 * r2 + r3 * r3;
    #pragma unroll
    for (int off = 16; off > 0; off >>= 1) s += __shfl_down_sync(0xffffffffu, s, off);
    __shared__ float ws[8];
    if ((tid & 31) == 0) ws[tid >> 5] = s;
    __syncthreads();
    if (tid == 0) {
        float tot = 0.0f;
        #pragma unroll
        for (int i = 0; i < 8; i++) tot += ws[i];
        atomicAdd(&g_loss[q], tot);
    }
}

// ---------------------------------------------------------------------------
// output: quantized_out (N,D,T) = x - residual_final  (transpose back)
// ---------------------------------------------------------------------------
__global__ void transpose_out_kernel(const float* __restrict__ x, float* __restrict__ out) {
    __shared__ float tile[32][33];
    int n  = blockIdx.z;
    int t0 = blockIdx.x * 32;
    int d0 = blockIdx.y * 32;
    int tx = threadIdx.x, ty = threadIdx.y;  // (32, 8)

    #pragma unroll
    for (int i = 0; i < 4; i++) {
        int t = t0 + ty + i * 8;
        size_t gi = (size_t)(n * TT + t) * DD + (d0 + tx);
        tile[ty + i * 8][tx] = __half2float(g_res_h[gi]) + __half2float(g_res_l[gi]);
    }
    __syncthreads();
    #pragma unroll
    for (int i = 0; i < 4; i++) {
        int d = d0 + ty + i * 8;
        size_t gi = (size_t)n * DD * TT + (size_t)d * TT + (t0 + tx);
        out[gi] = x[gi] - tile[tx][ty + i * 8];
    }
}

__global__ void idx_kernel(float* __restrict__ out) {
    int i = blockIdx.x * blockDim.x + threadIdx.x;
    if (i < OUT_IDX) out[OUT_QUANT + i] = (float)g_indices[i];
}

// all 6 perplexities + mean loss in one kernel
__global__ void finalize_kernel(float* __restrict__ out) {
    int tid = threadIdx.x;   // 256
    __shared__ float ws[8];
    __shared__ float perp_sum;
    if (tid == 0) perp_sum = 0.0f;
    __syncthreads();

    for (int q = 0; q < QQ; q++) {
        float s = 0.0f;
        for (int i = tid; i < CC; i += 256) {
            float p = (float)g_hist2[q * CC + i] * (1.0f / (float)NT);
            s += p * logf(p + 1e-10f);
        }
        #pragma unroll
        for (int off = 16; off > 0; off >>= 1) s += __shfl_down_sync(0xffffffffu, s, off);
        if ((tid & 31) == 0) ws[tid >> 5] = s;
        __syncthreads();
        if (tid == 0) {
            float t = 0.0f;
            #pragma unroll
            for (int i = 0; i < 8; i++) t += ws[i];
            perp_sum += expf(-t);
        }
        __syncthreads();
    }

    if (tid == 0) {
        float l = 0.0f;
        #pragma unroll
        for (int q = 0; q < QQ; q++) l += g_loss[q];
        out[OUT_QUANT + OUT_IDX + 0] = l / ((float)NT * (float)DD) / (float)QQ;
        out[OUT_QUANT + OUT_IDX + 1] = perp_sum / (float)QQ;
    }
}

// ---------------------------------------------------------------------------
extern "C" void kernel_launch(void* const* d_in, const int* in_sizes, int n_in,
                              void* d_out, int out_size) {
    const float* x  = (const float*)d_in[0];   // (64, 512, 256) fp32
    const float* cb = (const float*)d_in[1];   // (6, 1024, 512) fp32
    float* out = (float*)d_out;

    static bool attr_set = false;
    if (!attr_set) {
        cudaFuncSetAttribute(argmin_kernel,
                             cudaFuncAttributeMaxDynamicSharedMemorySize, ARG_SMEM);
        attr_set = true;
    }

    init_kernel<<<64, 256>>>();

    dim3 tb(32, 8);
    dim3 tg(TT / 32, DD / 32, NN);   // (8, 16, 64)
    transpose_in_kernel<<<tg, tb>>>(x);

    cbprep_kernel<<<QQ * CC, 128>>>(cb);

    for (int q = 0; q < QQ; q++) {
        const float* cbq = cb + (size_t)q * CC * DD;
        dim3 ag(NT / MROWS, CC / NCODES);   // (256, 8)
        argmin_kernel<<<ag, 256, ARG_SMEM>>>(q);
        update_kernel<<<NT / 2, 256>>>(cbq, q);
    }

    transpose_out_kernel<<<tg, tb>>>(x, out);
    idx_kernel<<<(OUT_IDX + 255) / 256, 256>>>(out);
    finalize_kernel<<<1, 256>>>(out);
}